// round 17
// baseline (speedup 1.0000x reference)
#include <cuda_runtime.h>
#include <cuda_fp16.h>
#include <cstdint>
#include <cstddef>

// Legacy-path fused NeuralCTLSTM, v15: v14 base (fp16, 12 warps, m32 x n16
// x 7g, warp-private 3-stage cp.async rings, W resident, epilogue staging)
// with the per-chunk serial LDS chain removed:
//  - A fragments loaded via ldmatrix.m8n8.x4 (4 LDSM vs 16 LDS.32)
//  - cross-chunk A-frag software pipeline: chunk ch+1's frags are LDSM'd
//    during chunk ch's MMA stream (a_cur/a_next rotation, rolling stages)
// Grid (16, 9) = 144 CTAs = one wave.

#define NG 7
#define HH 256
#define BK 32
#define NCHUNK 8
#define THREADS 384
#define GYS 9
#define STREAMS (12 * GYS)                  // 108 warp-streams per o-block

#define OFF_BIAS 0                          // 112 floats + pad = 512B
#define OFF_W 512
#define W_BYTES (NG * NCHUNK * 2 * 512)     // 112 frag-units x 512B = 57344
#define A_P_B 80                            // A stage row stride (bytes)
#define A_STAGE_B (32 * A_P_B)              // 2560
#define NSTAGE 3
#define A_WARP_B (NSTAGE * A_STAGE_B)       // 7680
#define OFF_A (OFF_W + W_BYTES)             // 57856
#define C_STRIDE_F 20                       // 80B row stride (16B-aligned)
#define C_ARR_B (32 * C_STRIDE_F * 4)       // 2560
#define C_WARP_B (2 * C_ARR_B + 128)        // c, cbar, dt = 5248
#define OFF_C (OFF_A + 12 * A_WARP_B)       // 150016
#define SMEM_BYTES (OFF_C + 12 * C_WARP_B)  // 212992

// fp16 copy of h_ti (B x H = 16.78M halfs = 32MB scratch)
__device__ __align__(16) __half2 g_h16[(65536 * 256) / 2];

__device__ __forceinline__ uint32_t pack_h2(float a, float b) {
    __half2 h = __floats2half2_rn(a, b);
    return *reinterpret_cast<uint32_t*>(&h);
}

__device__ __forceinline__ void mma_f16(float* d, const uint32_t* a,
                                        uint32_t b0, uint32_t b1) {
    asm volatile(
        "mma.sync.aligned.m16n8k16.row.col.f32.f16.f16.f32 "
        "{%0,%1,%2,%3}, {%4,%5,%6,%7}, {%8,%9}, {%0,%1,%2,%3};\n"
        : "+f"(d[0]), "+f"(d[1]), "+f"(d[2]), "+f"(d[3])
        : "r"(a[0]), "r"(a[1]), "r"(a[2]), "r"(a[3]), "r"(b0), "r"(b1));
}

__device__ __forceinline__ void ldsm_x4(uint32_t* r, uint32_t addr) {
    asm volatile(
        "ldmatrix.sync.aligned.m8n8.x4.shared.b16 {%0,%1,%2,%3}, [%4];\n"
        : "=r"(r[0]), "=r"(r[1]), "=r"(r[2]), "=r"(r[3]) : "r"(addr));
}

__device__ __forceinline__ void cp_async16(uint32_t dst, const void* src) {
    asm volatile("cp.async.cg.shared.global [%0], [%1], 16;\n"
                 :: "r"(dst), "l"(src) : "memory");
}

__device__ __forceinline__ float tanh_fast(float x) {
    float y;
    asm("tanh.approx.f32 %0, %1;" : "=f"(y) : "f"(x));
    return y;
}
__device__ __forceinline__ float sigm(float x) {       // 0.5*tanh(x/2)+0.5
    return fmaf(tanh_fast(0.5f * x), 0.5f, 0.5f);
}

// ---- pre-pass: h_ti fp32 -> fp16 scratch (8 elems/thread) ----
extern "C" __global__ void __launch_bounds__(256, 1)
nctlstm_cvt_kernel(const float* __restrict__ src, int n8)
{
    const int i = blockIdx.x * 256 + threadIdx.x;
    if (i < n8) {
        const float4 f0 = reinterpret_cast<const float4*>(src)[2 * i];
        const float4 f1 = reinterpret_cast<const float4*>(src)[2 * i + 1];
        g_h16[4 * i + 0] = __floats2half2_rn(f0.x, f0.y);
        g_h16[4 * i + 1] = __floats2half2_rn(f0.z, f0.w);
        g_h16[4 * i + 2] = __floats2half2_rn(f1.x, f1.y);
        g_h16[4 * i + 3] = __floats2half2_rn(f1.z, f1.w);
    }
}

extern "C" __global__ void __launch_bounds__(THREADS, 1)
nctlstm_v15_kernel(const float* __restrict__ inter_times,
                   const float* __restrict__ c_ti,
                   const float* __restrict__ cbar,
                   const float* __restrict__ W,
                   const float* __restrict__ bias,
                   float* __restrict__ out,
                   int Btot)
{
    extern __shared__ char smem[];
    const uint32_t sb = (uint32_t)__cvta_generic_to_shared(smem);

    const int tid  = threadIdx.x;
    const int warp = tid >> 5;       // 0..11
    const int lane = tid & 31;
    const int grp  = lane >> 2;      // 0..7
    const int tig  = lane & 3;       // 0..3

    const int o0 = blockIdx.x * 16;
    const int stream = blockIdx.y * 12 + warp;   // 0..107
    const int nblk = Btot >> 5;                  // 2048 32-row blocks

    const __half* h16 = reinterpret_cast<const __half*>(g_h16);

    const float* bias_s = reinterpret_cast<const float*>(smem + OFF_BIAS);
    const uint4* wperm = reinterpret_cast<const uint4*>(smem + OFF_W);
    uint4* wperm_w = reinterpret_cast<uint4*>(smem + OFF_W);
    const uint32_t warpA = sb + OFF_A + (uint32_t)warp * A_WARP_B;
    const uint32_t warpC = sb + OFF_C + (uint32_t)warp * C_WARP_B;
    const float*  c_s  = reinterpret_cast<const float*>(smem + OFF_C + warp * C_WARP_B);
    const float*  cb_s = c_s + (C_ARR_B / 4);
    const float*  dt_s = cb_s + (C_ARR_B / 4);

    // per-lane ldmatrix offset: rows (lane&15), k-half (lane>>4)
    const uint32_t lds_lane = (uint32_t)((lane & 15) * A_P_B + (lane >> 4) * 16);

    // ---- warp-private A chunk loader: 32 rows x 32 halfs, 4 cp.async/lane --
    auto load_chunk = [&](int rb, int ch, int s) {
        const uint32_t ab = warpA + (uint32_t)s * A_STAGE_B;
        const __half* src = h16 + ((size_t)rb << 5) * HH + ch * BK;
#pragma unroll
        for (int i = 0; i < 4; i++) {
            const int idx = lane + i * 32;        // 0..127
            const int r = idx >> 2, g16 = idx & 3;
            cp_async16(ab + (uint32_t)(r * A_P_B + g16 * 16),
                       src + (size_t)r * HH + g16 * 8);
        }
        asm volatile("cp.async.commit_group;\n" ::: "memory");
    };

    // ---- A-fragment LDSM: 4x ldmatrix.x4 -> a[ks][mt][4] ----
    auto load_frags = [&](uint32_t a[2][2][4], int s) {
        const uint32_t ab = warpA + (uint32_t)s * A_STAGE_B + lds_lane;
#pragma unroll
        for (int ks = 0; ks < 2; ks++)
#pragma unroll
            for (int mt = 0; mt < 2; mt++)
                ldsm_x4(a[ks][mt], ab + (uint32_t)(mt * 16 * A_P_B + ks * 32));
    };

    // ---- epilogue-operand stager (NO commit; joins caller's group) ----
    auto load_cblock = [&](int rb) {
        const float* csrc  = c_ti + ((size_t)rb << 5) * HH + o0;
        const float* cbsrc = cbar + ((size_t)rb << 5) * HH + o0;
#pragma unroll
        for (int i = 0; i < 4; i++) {
            const int idx = lane + i * 32;        // 0..127
            const int r = idx >> 2, cg = idx & 3;
            cp_async16(warpC + (uint32_t)(r * (C_STRIDE_F * 4) + cg * 16),
                       csrc + (size_t)r * HH + cg * 4);
            cp_async16(warpC + (uint32_t)(C_ARR_B + r * (C_STRIDE_F * 4) + cg * 16),
                       cbsrc + (size_t)r * HH + cg * 4);
        }
        if (lane < 8)
            cp_async16(warpC + (uint32_t)(2 * C_ARR_B + lane * 16),
                       inter_times + (rb << 5) + lane * 4);
    };

    // prologue: first three chunks of first block in flight during W permute
    const int rb0 = stream;
    load_chunk(rb0, 0, 0);
    load_chunk(rb0, 1, 1);
    load_chunk(rb0, 2, 2);

    // ---- one-time W permute to fp16 k16-frag order (112 units) ----
    for (int u = warp; u < NG * NCHUNK * 2; u += 12) {
        const int nh = u & 1, ch = (u >> 1) & 7, g = u >> 4;
        const int o = o0 + nh * 8 + grp;
        const float* ws = W + ((size_t)g * HH + o) * HH + ch * 32 + 2 * tig;
        uint4 v;
        v.x = pack_h2(ws[0],  ws[1]);
        v.y = pack_h2(ws[8],  ws[9]);
        v.z = pack_h2(ws[16], ws[17]);
        v.w = pack_h2(ws[24], ws[25]);
        wperm_w[u * 32 + lane] = v;
    }

    // bias -> smem (112 floats, fp32)
    if (tid < NG * 16) {
        float* bw = reinterpret_cast<float*>(smem + OFF_BIAS);
        bw[tid] = bias[(size_t)(tid >> 4) * HH + o0 + (tid & 15)];
    }

    __syncthreads();   // W permute + bias visible; only block barrier

    const size_t BHtot = (size_t)Btot * HH;

    // ---- A-frag pipeline state: a_cur holds the frags of the chunk about
    // to be multiplied; s_cur is that chunk's stage (rolling mod 3 across
    // blocks). Prologue: wait chunk0, LDSM its frags.
    uint32_t a_cur[2][2][4], a_next[2][2][4];
    asm volatile("cp.async.wait_group 2;\n" ::: "memory");
    load_frags(a_cur, 0);
    int s_cur = 0;

    for (int rb = rb0; rb < nblk; rb += STREAMS) {
        float acc[NG][2][2][4];          // [g][nh][mt][frag]
#pragma unroll
        for (int g = 0; g < NG; g++)
#pragma unroll
            for (int nh = 0; nh < 2; nh++) {
                const float2 bb = *reinterpret_cast<const float2*>(
                    bias_s + g * 16 + nh * 8 + 2 * tig);
#pragma unroll
                for (int mt = 0; mt < 2; mt++) {
                    acc[g][nh][mt][0] = bb.x; acc[g][nh][mt][1] = bb.y;
                    acc[g][nh][mt][2] = bb.x; acc[g][nh][mt][3] = bb.y;
                }
            }

#pragma unroll 1
        for (int ch = 0; ch < NCHUNK; ch++) {
            // 1) prefetch chunk ch+3 into s_cur (its frags already in a_cur;
            //    LDSM of this stage happened last iteration -> WAR safe).
            //    ch 0 also stages this block's epilogue operands (same group).
            {
                if (ch == 0) load_cblock(rb);
                int c2 = ch + NSTAGE, r2 = rb;
                if (c2 >= NCHUNK) { c2 -= NCHUNK; r2 += STREAMS; }
                if (r2 < nblk) load_chunk(r2, c2, s_cur);
                else           asm volatile("cp.async.commit_group;\n" ::: "memory");
            }

            // 2) wait until chunk ch+1's stage is resident, LDSM its frags
            //    (overlaps this chunk's MMA stream below). Tail iterations
            //    read a stale-but-allocated stage; values unused.
            asm volatile("cp.async.wait_group 2;\n" ::: "memory");
            const int s_nxt = (s_cur + 1 == NSTAGE) ? 0 : s_cur + 1;
            load_frags(a_next, s_nxt);

            // 3) 14 LDS.128 (W frags) + 56 MMAs on a_cur
            const uint4* wch = wperm + (size_t)ch * 2 * 32 + lane;
#pragma unroll
            for (int g = 0; g < NG; g++) {
                const uint4 wf0 = wch[(size_t)g * 16 * 32];
                const uint4 wf1 = wch[(size_t)g * 16 * 32 + 32];
                mma_f16(acc[g][0][0], a_cur[0][0], wf0.x, wf0.y);
                mma_f16(acc[g][0][1], a_cur[0][1], wf0.x, wf0.y);
                mma_f16(acc[g][0][0], a_cur[1][0], wf0.z, wf0.w);
                mma_f16(acc[g][0][1], a_cur[1][1], wf0.z, wf0.w);
                mma_f16(acc[g][1][0], a_cur[0][0], wf1.x, wf1.y);
                mma_f16(acc[g][1][1], a_cur[0][1], wf1.x, wf1.y);
                mma_f16(acc[g][1][0], a_cur[1][0], wf1.z, wf1.w);
                mma_f16(acc[g][1][1], a_cur[1][1], wf1.z, wf1.w);
            }

            // 4) rotate
#pragma unroll
            for (int ks = 0; ks < 2; ks++)
#pragma unroll
                for (int mt = 0; mt < 2; mt++)
#pragma unroll
                    for (int q = 0; q < 4; q++)
                        a_cur[ks][mt][q] = a_next[ks][mt][q];
            s_cur = s_nxt;
        }

        // ---- fused epilogue: all operands in smem (staged in chunk 0) ----
#pragma unroll
        for (int mt = 0; mt < 2; mt++) {
#pragma unroll
            for (int rs = 0; rs < 2; rs++) {
                const int row = mt * 16 + grp + rs * 8;       // 0..31
                const int b = rb * 32 + row;
                const float dt = dt_s[row];
#pragma unroll
                for (int nh = 0; nh < 2; nh++) {
                    const int col = nh * 8 + 2 * tig;
                    const float2 cv = *reinterpret_cast<const float2*>(
                        c_s + row * C_STRIDE_F + col);
                    const float2 cb = *reinterpret_cast<const float2*>(
                        cb_s + row * C_STRIDE_F + col);
                    const size_t base = (size_t)b * HH + o0 + col;

                    float2 r_o, r_h, r_c, r_cb, r_d;
#pragma unroll
                    for (int j = 0; j < 2; j++) {
                        const int ai = rs * 2 + j;
                        const float gi  = acc[0][nh][mt][ai];
                        const float gf  = acc[1][nh][mt][ai];
                        const float go  = acc[2][nh][mt][ai];
                        const float gib = acc[3][nh][mt][ai];
                        const float gfb = acc[4][nh][mt][ai];
                        const float gz  = acc[5][nh][mt][ai];
                        const float gd  = acc[6][nh][mt][ai];

                        const float i_g  = sigm(gi);
                        const float f_g  = sigm(gf);
                        const float o_g  = sigm(go);
                        const float ib_g = sigm(gib);
                        const float fb_g = sigm(gfb);
                        const float z    = tanh_fast(gz);
                        const float decay = fmaxf(gd, 0.0f)
                                          + __logf(1.0f + __expf(-fabsf(gd)));

                        const float ct  = (j == 0) ? cv.x : cv.y;
                        const float cbv = (j == 0) ? cb.x : cb.y;

                        const float e       = __expf(-decay * dt);
                        const float c_after = cbv + (ct - cbv) * e;
                        const float c_new   = f_g * c_after + i_g * z;
                        const float cb_new  = fb_g * cbv + ib_g * z;
                        const float h_new   = o_g * tanh_fast(c_after);

                        if (j == 0) { r_o.x = o_g; r_h.x = h_new; r_c.x = c_new; r_cb.x = cb_new; r_d.x = decay; }
                        else        { r_o.y = o_g; r_h.y = h_new; r_c.y = c_new; r_cb.y = cb_new; r_d.y = decay; }
                    }
                    __stcs(reinterpret_cast<float2*>(out + 0 * BHtot + base), r_o);
                    __stcs(reinterpret_cast<float2*>(out + 1 * BHtot + base), r_h);
                    __stcs(reinterpret_cast<float2*>(out + 2 * BHtot + base), r_c);
                    __stcs(reinterpret_cast<float2*>(out + 3 * BHtot + base), r_cb);
                    __stcs(reinterpret_cast<float2*>(out + 4 * BHtot + base), r_d);
                }
            }
        }
    }
}

extern "C" void kernel_launch(void* const* d_in, const int* in_sizes, int n_in,
                              void* d_out, int out_size)
{
    const float* inter_times = (const float*)d_in[0];
    const float* h_ti        = (const float*)d_in[1];
    const float* c_ti        = (const float*)d_in[2];
    const float* cbar        = (const float*)d_in[3];
    const float* W           = (const float*)d_in[4];
    const float* bias        = (const float*)d_in[5];
    const int B = in_sizes[0];

    // pre-pass: h_ti -> fp16 scratch
    const int n8 = (B * HH) / 8;
    nctlstm_cvt_kernel<<<(n8 + 255) / 256, 256>>>(h_ti, n8);

    cudaFuncSetAttribute(nctlstm_v15_kernel,
                         cudaFuncAttributeMaxDynamicSharedMemorySize, SMEM_BYTES);

    dim3 grid(16, GYS);   // 144 CTAs = one wave; one 16-col o-block per CTA
    nctlstm_v15_kernel<<<grid, THREADS, SMEM_BYTES>>>(
        inter_times, c_ti, cbar, W, bias, (float*)d_out, B);
}